// round 3
// baseline (speedup 1.0000x reference)
#include <cuda_runtime.h>
#include <stdint.h>

#define THREADS 512
#define NBINS   2048
#define BSHIFT  21            // key >> 21 -> 2048 bins
#define CAP     256
#define FDIM    8192
#define EPT     16
#define VPT     4

// Order-preserving float -> uint32 (ascending)
__device__ __forceinline__ unsigned f2key(float f) {
    unsigned u = __float_as_uint(f);
    return u ^ ((unsigned)((int)u >> 31) | 0x80000000u);
}
// Exact inverse
__device__ __forceinline__ float key2f(unsigned k) {
    unsigned m = (~(unsigned)((int)k >> 31)) | 0x80000000u;
    return __uint_as_float(k ^ m);
}

__global__ __launch_bounds__(THREADS, 4)
void topk_mask_kernel(const float* __restrict__ x, const float* __restrict__ w,
                      const int* __restrict__ kp, float* __restrict__ out)
{
    __shared__ __align__(16) unsigned keys[FDIM];     // 32 KB
    __shared__ __align__(16) unsigned hist[NBINS];    // 8 KB
    __shared__ unsigned part[THREADS];                // 2 KB
    __shared__ unsigned listKH[CAP], listIH[CAP], listKL[CAP], listIL[CAP]; // 4 KB
    __shared__ int s_cntH, s_cntL;
    __shared__ int s_Bh, s_Bl, s_rh, s_rl;
    __shared__ unsigned s_Th, s_Ih, s_Tl, s_Il;
    __shared__ int s_red;
    __shared__ int s_K;

    const int tid  = threadIdx.x;
    const int lane = tid & 31;
    const int warp = tid >> 5;
    const int b    = blockIdx.x;

    if (tid == 0) { s_cntH = 0; s_cntL = 0; s_K = kp ? kp[0] : 64; }
    ((uint4*)hist)[tid] = make_uint4(0,0,0,0);   // 2048 words = 512 * uint4
    __syncthreads();
    const int K = s_K;

    const float4* xr = (const float4*)(x + (size_t)b * FDIM);
    const float4* wr = (const float4*)w;
    float4* orow     = (float4*)(out + (size_t)b * FDIM);

    // ---- Phase 0: load, multiply, key -> smem, histogram ----
    #pragma unroll
    for (int k = 0; k < VPT; k++) {
        int v = tid + k * THREADS;
        float4 xv = xr[v];
        float4 wv = wr[v];
        unsigned k0 = f2key(xv.x * wv.x);
        unsigned k1 = f2key(xv.y * wv.y);
        unsigned k2 = f2key(xv.z * wv.z);
        unsigned k3 = f2key(xv.w * wv.w);
        ((uint4*)keys)[v] = make_uint4(k0, k1, k2, k3);
        atomicAdd(&hist[k0 >> BSHIFT], 1u);
        atomicAdd(&hist[k1 >> BSHIFT], 1u);
        atomicAdd(&hist[k2 >> BSHIFT], 1u);
        atomicAdd(&hist[k3 >> BSHIFT], 1u);
    }
    __syncthreads();

    // ---- Phase 1a: partial sums, 4 bins per thread ----
    {
        uint4 a = ((const uint4*)hist)[tid];
        part[tid] = a.x + a.y + a.z + a.w;
    }
    __syncthreads();

    // ---- Phase 1b: boundary bins. warp0 = top (desc), warp1 = bottom (asc) ----
    if (warp == 0) {
        unsigned g = 0;
        #pragma unroll
        for (int p = 0; p < 16; p++) g += part[lane*16 + p];
        unsigned acc = g;
        #pragma unroll
        for (int off = 1; off < 32; off <<= 1) {
            unsigned vv = __shfl_down_sync(0xFFFFFFFFu, acc, off);
            if (lane + off < 32) acc += vv;
        }
        unsigned above = acc - g;
        if ((int)above < K && (int)(above + g) >= K) {
            unsigned run = above;
            int base = lane * 16;
            for (int p = 15; p >= 0; --p) {
                unsigned pc = part[base + p];
                if ((int)(run + pc) >= K) {
                    int bb = (base + p) * 4;
                    for (int b4 = 3; b4 >= 0; --b4) {
                        unsigned c = hist[bb + b4];
                        if ((int)(run + c) >= K) { s_Bh = bb + b4; s_rh = K - (int)run; break; }
                        run += c;
                    }
                    break;
                }
                run += pc;
            }
        }
    } else if (warp == 1) {
        unsigned g = 0;
        #pragma unroll
        for (int p = 0; p < 16; p++) g += part[lane*16 + p];
        unsigned acc = g;
        #pragma unroll
        for (int off = 1; off < 32; off <<= 1) {
            unsigned vv = __shfl_up_sync(0xFFFFFFFFu, acc, off);
            if (lane >= off) acc += vv;
        }
        unsigned below = acc - g;
        if ((int)below < K && (int)(below + g) >= K) {
            unsigned run = below;
            int base = lane * 16;
            for (int p = 0; p < 16; ++p) {
                unsigned pc = part[base + p];
                if ((int)(run + pc) >= K) {
                    int bb = (base + p) * 4;
                    for (int b4 = 0; b4 < 4; ++b4) {
                        unsigned c = hist[bb + b4];
                        if ((int)(run + c) >= K) { s_Bl = bb + b4; s_rl = K - (int)run; break; }
                        run += c;
                    }
                    break;
                }
                run += pc;
            }
        }
    }
    __syncthreads();

    // ---- Phase 2: compact boundary-bin candidates ----
    {
        const unsigned Bh = (unsigned)s_Bh, Bl = (unsigned)s_Bl;
        #pragma unroll
        for (int k = 0; k < VPT; k++) {
            int v = tid + k * THREADS;
            uint4 kv = ((const uint4*)keys)[v];
            unsigned kk[4] = { kv.x, kv.y, kv.z, kv.w };
            #pragma unroll
            for (int c = 0; c < 4; c++) {
                unsigned bin = kk[c] >> BSHIFT;
                if (bin == Bh) { int p = atomicAdd(&s_cntH, 1); if (p < CAP) { listKH[p] = kk[c]; listIH[p] = (unsigned)(4*v + c); } }
                if (bin == Bl) { int p = atomicAdd(&s_cntL, 1); if (p < CAP) { listKL[p] = kk[c]; listIL[p] = (unsigned)(4*v + c); } }
            }
        }
    }
    __syncthreads();

    const int nH = s_cntH, nL = s_cntL;
    const bool ovH = nH > CAP, ovL = nL > CAP;

    // ---- Phase 3: exact threshold + tie index cutoff (tiny O(n^2) rank) ----
    if (!ovH && tid < nH) {
        unsigned kj = listKH[tid], ij = listIH[tid];
        int rank = 0;
        for (int i = 0; i < nH; i++) {
            unsigned ki = listKH[i], ii = listIH[i];
            rank += (ki > kj) || (ki == kj && ii < ij);
        }
        if (rank == s_rh - 1) { s_Th = kj; s_Ih = ij; }
    }
    if (!ovL && tid < nL) {
        unsigned kj = listKL[tid], ij = listIL[tid];
        int rank = 0;
        for (int i = 0; i < nL; i++) {
            unsigned ki = listKL[i], ii = listIL[i];
            rank += (ki < kj) || (ki == kj && ii < ij);
        }
        if (rank == s_rl - 1) { s_Tl = kj; s_Il = ij; }
    }

    // ---- Rare exact fallback (degenerate distributions): binary search ----
    if (ovH) {
        unsigned lo = 0, hi = 0xFFFFFFFFu;
        for (int it = 0; it < 32; ++it) {
            unsigned mid = lo + ((hi - lo) >> 1);
            if (tid == 0) s_red = 0;
            __syncthreads();
            int c = 0;
            for (int i = tid; i < FDIM; i += THREADS) c += (keys[i] > mid);
            c = __reduce_add_sync(0xFFFFFFFFu, c);
            if (lane == 0) atomicAdd(&s_red, c);
            __syncthreads();
            int tot = s_red; __syncthreads();
            if (tot >= K) lo = mid + 1; else hi = mid;
        }
        unsigned Th = lo;
        if (tid == 0) s_red = 0;
        __syncthreads();
        { int c = 0;
          for (int i = tid; i < FDIM; i += THREADS) c += (keys[i] > Th);
          c = __reduce_add_sync(0xFFFFFFFFu, c);
          if (lane == 0) atomicAdd(&s_red, c); }
        __syncthreads();
        int r = K - s_red; __syncthreads();
        unsigned lo2 = 0, hi2 = FDIM - 1;
        for (int it = 0; it < 13; ++it) {
            unsigned mid = lo2 + ((hi2 - lo2) >> 1);
            if (tid == 0) s_red = 0;
            __syncthreads();
            int c = 0;
            for (int i = tid; i < FDIM; i += THREADS) c += (keys[i] == Th && (unsigned)i <= mid);
            c = __reduce_add_sync(0xFFFFFFFFu, c);
            if (lane == 0) atomicAdd(&s_red, c);
            __syncthreads();
            int tot = s_red; __syncthreads();
            if (tot >= r) hi2 = mid; else lo2 = mid + 1;
        }
        if (tid == 0) { s_Th = Th; s_Ih = lo2; }
    }
    if (ovL) {
        unsigned lo = 0, hi = 0xFFFFFFFFu;
        for (int it = 0; it < 32; ++it) {
            unsigned mid = lo + ((hi - lo) >> 1);
            if (tid == 0) s_red = 0;
            __syncthreads();
            int c = 0;
            for (int i = tid; i < FDIM; i += THREADS) c += (keys[i] <= mid);
            c = __reduce_add_sync(0xFFFFFFFFu, c);
            if (lane == 0) atomicAdd(&s_red, c);
            __syncthreads();
            int tot = s_red; __syncthreads();
            if (tot >= K) hi = mid; else lo = mid + 1;
        }
        unsigned Tl = lo;
        if (tid == 0) s_red = 0;
        __syncthreads();
        { int c = 0;
          for (int i = tid; i < FDIM; i += THREADS) c += (keys[i] < Tl);
          c = __reduce_add_sync(0xFFFFFFFFu, c);
          if (lane == 0) atomicAdd(&s_red, c); }
        __syncthreads();
        int r = K - s_red; __syncthreads();
        unsigned lo2 = 0, hi2 = FDIM - 1;
        for (int it = 0; it < 13; ++it) {
            unsigned mid = lo2 + ((hi2 - lo2) >> 1);
            if (tid == 0) s_red = 0;
            __syncthreads();
            int c = 0;
            for (int i = tid; i < FDIM; i += THREADS) c += (keys[i] == Tl && (unsigned)i <= mid);
            c = __reduce_add_sync(0xFFFFFFFFu, c);
            if (lane == 0) atomicAdd(&s_red, c);
            __syncthreads();
            int tot = s_red; __syncthreads();
            if (tot >= r) hi2 = mid; else lo2 = mid + 1;
        }
        if (tid == 0) { s_Tl = Tl; s_Il = lo2; }
    }
    __syncthreads();

    // ---- Phase 4: masked write-out ----
    const unsigned Th = s_Th, Ih = s_Ih, Tl = s_Tl, Il = s_Il;
    #pragma unroll
    for (int k = 0; k < VPT; k++) {
        int v = tid + k * THREADS;
        uint4 kv = ((const uint4*)keys)[v];
        unsigned kk[4] = { kv.x, kv.y, kv.z, kv.w };
        float vals[4];
        #pragma unroll
        for (int c = 0; c < 4; c++) {
            unsigned idx = (unsigned)(4*v + c);
            bool z = (kk[c] > Th) || (kk[c] < Tl) ||
                     (kk[c] == Th && idx <= Ih) ||
                     (kk[c] == Tl && idx <= Il);
            vals[c] = z ? 0.0f : key2f(kk[c]);
        }
        float4 o; o.x = vals[0]; o.y = vals[1]; o.z = vals[2]; o.w = vals[3];
        orow[v] = o;
    }
}

extern "C" void kernel_launch(void* const* d_in, const int* in_sizes, int n_in,
                              void* d_out, int out_size)
{
    const float* x = (const float*)d_in[0];
    const float* w = (const float*)d_in[1];
    const int* kp  = (n_in >= 3) ? (const int*)d_in[2] : nullptr;

    int Fdim = in_sizes[1];
    int B    = in_sizes[0] / Fdim;

    topk_mask_kernel<<<B, THREADS>>>(x, w, kp, (float*)d_out);
}